// round 7
// baseline (speedup 1.0000x reference)
#include <cuda_runtime.h>

#define T_STEPS 4096
#define H       1024
#define NG      7
#define GW      (NG * H)      // 7168 gate columns
#define KROWS   33
#define NB      128           // persistent blocks (1 per SM)
#define NT      256           // threads per block (8 warps)
#define UNITS   8             // hidden units per block
#define COLS    (UNITS * NG)  // 56 gate columns per block
#define KSUB    11            // emb rows per precompute block (3*11 = 33)

#define HREG    512                       // rows [0,512) live in registers
#define HSM     (H - HREG)                // 512 rows in SMEM
#define KREG    (HREG / 128)              // 4 float4 per lane per gate
#define KSM     (HSM / 128)               // 4 float4 per lane per gate
#define WS_FLOATS (COLS * HSM)            // 28672 floats = 112 KB

#define NBAR    8                         // split arrival counters
#define BAR_STRIDE 512                    // unsigneds: 2KB apart -> distinct L2 slices

// -------- device scratch (no allocations allowed) --------
__device__ float    g_pre[KROWS * GW];   // precomputed input contribution + bias
__device__ float    g_h[2 * H];          // double-buffered h_d
__device__ __align__(128) unsigned g_bars[NBAR * BAR_STRIDE]; // split step counters

// -------- helpers --------
__device__ __forceinline__ unsigned ld_acquire_u32(const unsigned* p) {
    unsigned v;
    asm volatile("ld.acquire.gpu.u32 %0, [%1];" : "=r"(v) : "l"(p));
    return v;
}
__device__ __forceinline__ float sigmoidf_(float x) {
    return __fdividef(1.0f, 1.0f + __expf(-x));
}
__device__ __forceinline__ float tanhf_(float x) {
    return 1.0f - __fdividef(2.0f, __expf(2.0f * x) + 1.0f);
}
__device__ __forceinline__ float softplusf_(float x) {
    return fmaxf(x, 0.0f) + __logf(1.0f + __expf(-fabsf(x)));
}

// -------- kernel 1: pre[k][j] = emb[k] @ W_top[:,j] + b_r[j]  (+ state reset) --------
__global__ void pre_kernel(const float* __restrict__ w_r,
                           const float* __restrict__ b_r,
                           const float* __restrict__ emb) {
    // graph-replay determinism: block (0,0) resets persistent state
    if (blockIdx.x == 0 && blockIdx.y == 0) {
        if (threadIdx.x < NBAR) g_bars[threadIdx.x * BAR_STRIDE] = 0u;
        for (int i = threadIdx.x; i < 2 * H; i += NT) g_h[i] = 0.0f;
    }

    __shared__ float es[KSUB * H];
    const int j  = blockIdx.x * NT + threadIdx.x;   // gate column
    const int k0 = blockIdx.y * KSUB;               // emb row base

    for (int idx = threadIdx.x; idx < KSUB * H; idx += NT)
        es[idx] = emb[k0 * H + idx];
    __syncthreads();

    float acc[KSUB];
#pragma unroll
    for (int k = 0; k < KSUB; ++k) acc[k] = 0.0f;

    const float4* es4 = (const float4*)es;
    for (int i4 = 0; i4 < H / 4; ++i4) {
        const int i = i4 * 4;
        const float w0 = w_r[(i + 0) * GW + j];
        const float w1 = w_r[(i + 1) * GW + j];
        const float w2 = w_r[(i + 2) * GW + j];
        const float w3 = w_r[(i + 3) * GW + j];
#pragma unroll
        for (int k = 0; k < KSUB; ++k) {
            float4 e = es4[k * (H / 4) + i4];
            acc[k] = fmaf(w0, e.x, fmaf(w1, e.y, fmaf(w2, e.z, fmaf(w3, e.w, acc[k]))));
        }
    }
    const float b = b_r[j];
#pragma unroll
    for (int k = 0; k < KSUB; ++k)
        g_pre[(k0 + k) * GW + j] = acc[k] + b;
}

// -------- kernel 2: persistent sequential CTLSTM --------
__global__ void __launch_bounds__(NT, 1)
ctlstm_kernel(const int*   __restrict__ event,
              const float* __restrict__ duration,
              const float* __restrict__ w_r,
              float*       __restrict__ out) {
    extern __shared__ float Ws[];   // [COLS][HSM] : weights for rows [512,1024)

    const int tid  = threadIdx.x;
    const int lane = tid & 31;
    const int w    = tid >> 5;                  // warp id 0..7 -> local unit
    const int n    = blockIdx.x * UNITS + w;    // global hidden unit

    unsigned* my_bar = &g_bars[(blockIdx.x & (NBAR - 1)) * BAR_STRIDE];

    // --- one-time: rows [512,1024) into SMEM ---
    for (int idx = tid; idx < WS_FLOATS; idx += NT) {
        const int c  = idx / HSM;
        const int ii = idx - c * HSM;
        const int wu = c / NG;
        const int g  = c - wu * NG;
        Ws[idx] = w_r[(size_t)(H + HREG + ii) * GW + g * H + blockIdx.x * UNITS + wu];
    }

    // --- one-time: rows [0,512) into registers (112 floats/thread) ---
    float4 wreg[NG * KREG];
#pragma unroll
    for (int g = 0; g < NG; ++g) {
#pragma unroll
        for (int k = 0; k < KREG; ++k) {
            const int i0 = 4 * (lane + 32 * k);
            const float* base = w_r + (size_t)(H + i0) * GW + g * H + n;
            wreg[g * KREG + k] = make_float4(base[0], base[GW],
                                             base[2 * (size_t)GW], base[3 * (size_t)GW]);
        }
    }
    __syncthreads();

    const float4* Wv = (const float4*)Ws + (w * NG) * (HSM / 4);

    float c_st = 0.0f, cb_st = 0.0f;  // per-unit recurrent state (valid in all lanes)

    for (int t = 0; t < T_STEPS; ++t) {
        // ---- input-only prefetch (in flight during the barrier wait) ----
        const int   e = __ldg(&event[t]);
        const float d = __ldg(&duration[t]);
        const float* prow = g_pre + (size_t)e * GW + n;
        float pregate[NG];
#pragma unroll
        for (int g = 0; g < NG; ++g)
            pregate[g] = __ldg(&prow[g * H]);

        // ---- wait for all blocks to finish step t-1 ----
        // single poller sums the 8 split counters (8 pipelined L2 loads)
        if (t > 0) {
            if (tid == 0) {
                const unsigned tgt = (unsigned)NB * (unsigned)t;
                for (;;) {
                    unsigned s = 0;
#pragma unroll
                    for (int k = 0; k < NBAR; ++k)
                        s += ld_acquire_u32(&g_bars[k * BAR_STRIDE]);
                    if (s >= tgt) break;
                }
            }
            __syncthreads();
        }

        // ---- broadcast h_d from L2 (written by other SMs) ----
        const float4* hp = (const float4*)(g_h + (t & 1) * H);
        float4 hx[8];
#pragma unroll
        for (int k = 0; k < 8; ++k) hx[k] = __ldcg(&hp[lane + 32 * k]);

        float acc[NG];
#pragma unroll
        for (int g = 0; g < NG; ++g) acc[g] = 0.0f;

        // rows [0,512): register-resident weights
#pragma unroll
        for (int k = 0; k < KREG; ++k) {
            const float4 h4 = hx[k];
#pragma unroll
            for (int g = 0; g < NG; ++g) {
                const float4 w4 = wreg[g * KREG + k];
                acc[g] = fmaf(w4.x, h4.x,
                         fmaf(w4.y, h4.y,
                         fmaf(w4.z, h4.z,
                         fmaf(w4.w, h4.w, acc[g]))));
            }
        }
        // rows [512,1024): SMEM-resident weights
#pragma unroll
        for (int k = 0; k < KSM; ++k) {
            const float4 h4 = hx[KREG + k];
#pragma unroll
            for (int g = 0; g < NG; ++g) {
                const float4 w4 = Wv[g * (HSM / 4) + lane + 32 * k];
                acc[g] = fmaf(w4.x, h4.x,
                         fmaf(w4.y, h4.y,
                         fmaf(w4.z, h4.z,
                         fmaf(w4.w, h4.w, acc[g]))));
            }
        }

        // warp reduction (all lanes end with full sums)
#pragma unroll
        for (int g = 0; g < NG; ++g) {
#pragma unroll
            for (int o = 16; o > 0; o >>= 1)
                acc[g] += __shfl_xor_sync(0xffffffffu, acc[g], o);
        }

        float gate[NG];
#pragma unroll
        for (int g = 0; g < NG; ++g)
            gate[g] = acc[g] + pregate[g];

        const float gi  = sigmoidf_(gate[0]);
        const float gf  = sigmoidf_(gate[1]);
        const float gz  = tanhf_(gate[2]);
        const float go  = sigmoidf_(gate[3]);
        const float gib = sigmoidf_(gate[4]);
        const float gfb = sigmoidf_(gate[5]);
        const float gdl = softplusf_(gate[6]);

        c_st  = gf  * c_st  + gi  * gz;
        cb_st = gfb * cb_st + gib * gz;
        const float h_t = go * tanhf_(c_st);
        const float cd  = cb_st + (c_st - cb_st) * __expf(-gdl * d);
        const float h_d = go * tanhf_(cd);

        if (lane == 0) {
            // critical value first
            g_h[((t + 1) & 1) * H + n] = h_d;
            const int TH = T_STEPS * H;
            float* o0 = out + t * H + n;
            o0[0 * TH] = h_t;
            o0[1 * TH] = c_st;
            o0[2 * TH] = cb_st;
            o0[3 * TH] = go;
            o0[4 * TH] = gdl;
        }

        __syncthreads();                 // all warps published their h_d
        if (tid == 0) {
            __threadfence();             // release h_d stores device-wide
            atomicAdd(my_bar, 1u);       // arrive on this block's split counter
        }
    }
}

// -------- launch --------
extern "C" void kernel_launch(void* const* d_in, const int* in_sizes, int n_in,
                              void* d_out, int out_size) {
    const int*   event    = (const int*)  d_in[0];
    const float* duration = (const float*)d_in[1];
    const float* w_r      = (const float*)d_in[2];
    const float* b_r      = (const float*)d_in[3];
    const float* emb      = (const float*)d_in[4];
    float*       out      = (float*)d_out;

    (void)in_sizes; (void)n_in; (void)out_size;

    const size_t smem = (size_t)WS_FLOATS * sizeof(float);  // 114688 B
    cudaFuncSetAttribute(ctlstm_kernel,
                         cudaFuncAttributeMaxDynamicSharedMemorySize,
                         (int)smem);

    pre_kernel<<<dim3(GW / NT, KROWS / KSUB), NT>>>(w_r, b_r, emb);
    ctlstm_kernel<<<NB, NT, smem>>>(event, duration, w_r, out);
}

// round 8
// speedup vs baseline: 1.2391x; 1.2391x over previous
#include <cuda_runtime.h>

#define T_STEPS 4096
#define H       1024
#define NG      7
#define GW      (NG * H)      // 7168 gate columns
#define KROWS   33
#define NB      128           // persistent blocks (1 per SM)
#define NT      256           // threads per block (8 warps)
#define UNITS   8             // hidden units per block
#define COLS    (UNITS * NG)  // 56 gate columns per block
#define KSUB    11            // emb rows per precompute block (3*11 = 33)

#define HREG    512                       // rows [0,512) live in registers
#define HSM     (H - HREG)                // 512 rows in SMEM
#define KREG    (HREG / 128)              // 4 float4 per lane per gate
#define KSM     (HSM / 128)               // 4 float4 per lane per gate
#define WS_FLOATS (COLS * HSM)            // 28672 floats = 112 KB

// -------- device scratch (no allocations allowed) --------
__device__ float    g_pre[KROWS * GW];   // precomputed input contribution + bias
__device__ float    g_h[2 * H];          // double-buffered h_d
__device__ __align__(128) unsigned g_count;              // arrival line (atomics only)
__device__ __align__(128) unsigned g_pad[64];            // keep lines apart
__device__ __align__(128) unsigned g_step;               // release line (read-only poll)

// -------- helpers --------
__device__ __forceinline__ unsigned ld_acquire_u32(const unsigned* p) {
    unsigned v;
    asm volatile("ld.acquire.gpu.u32 %0, [%1];" : "=r"(v) : "l"(p));
    return v;
}
__device__ __forceinline__ void st_release_u32(unsigned* p, unsigned v) {
    asm volatile("st.release.gpu.u32 [%0], %1;" :: "l"(p), "r"(v) : "memory");
}
__device__ __forceinline__ unsigned atom_acqrel_add(unsigned* p, unsigned v) {
    unsigned old;
    asm volatile("atom.acq_rel.gpu.global.add.u32 %0, [%1], %2;"
                 : "=r"(old) : "l"(p), "r"(v) : "memory");
    return old;
}
__device__ __forceinline__ float sigmoidf_(float x) {
    return __fdividef(1.0f, 1.0f + __expf(-x));
}
__device__ __forceinline__ float tanhf_(float x) {
    return 1.0f - __fdividef(2.0f, __expf(2.0f * x) + 1.0f);
}
__device__ __forceinline__ float softplusf_(float x) {
    return fmaxf(x, 0.0f) + __logf(1.0f + __expf(-fabsf(x)));
}

// -------- kernel 1: pre[k][j] = emb[k] @ W_top[:,j] + b_r[j]  (+ state reset) --------
__global__ void pre_kernel(const float* __restrict__ w_r,
                           const float* __restrict__ b_r,
                           const float* __restrict__ emb) {
    // graph-replay determinism: block (0,0) resets persistent state
    if (blockIdx.x == 0 && blockIdx.y == 0) {
        if (threadIdx.x == 0) { g_count = 0u; g_step = 0u; }
        for (int i = threadIdx.x; i < 2 * H; i += NT) g_h[i] = 0.0f;
    }

    __shared__ float es[KSUB * H];
    const int j  = blockIdx.x * NT + threadIdx.x;   // gate column
    const int k0 = blockIdx.y * KSUB;               // emb row base

    for (int idx = threadIdx.x; idx < KSUB * H; idx += NT)
        es[idx] = emb[k0 * H + idx];
    __syncthreads();

    float acc[KSUB];
#pragma unroll
    for (int k = 0; k < KSUB; ++k) acc[k] = 0.0f;

    const float4* es4 = (const float4*)es;
    for (int i4 = 0; i4 < H / 4; ++i4) {
        const int i = i4 * 4;
        const float w0 = w_r[(i + 0) * GW + j];
        const float w1 = w_r[(i + 1) * GW + j];
        const float w2 = w_r[(i + 2) * GW + j];
        const float w3 = w_r[(i + 3) * GW + j];
#pragma unroll
        for (int k = 0; k < KSUB; ++k) {
            float4 e = es4[k * (H / 4) + i4];
            acc[k] = fmaf(w0, e.x, fmaf(w1, e.y, fmaf(w2, e.z, fmaf(w3, e.w, acc[k]))));
        }
    }
    const float b = b_r[j];
#pragma unroll
    for (int k = 0; k < KSUB; ++k)
        g_pre[(k0 + k) * GW + j] = acc[k] + b;
}

// -------- kernel 2: persistent sequential CTLSTM --------
__global__ void __launch_bounds__(NT, 1)
ctlstm_kernel(const int*   __restrict__ event,
              const float* __restrict__ duration,
              const float* __restrict__ w_r,
              float*       __restrict__ out) {
    extern __shared__ float Ws[];   // [COLS][HSM] : weights for rows [512,1024)

    const int tid  = threadIdx.x;
    const int lane = tid & 31;
    const int w    = tid >> 5;                  // warp id 0..7 -> local unit
    const int n    = blockIdx.x * UNITS + w;    // global hidden unit

    // --- one-time: rows [512,1024) into SMEM ---
    for (int idx = tid; idx < WS_FLOATS; idx += NT) {
        const int c  = idx / HSM;
        const int ii = idx - c * HSM;
        const int wu = c / NG;
        const int g  = c - wu * NG;
        Ws[idx] = w_r[(size_t)(H + HREG + ii) * GW + g * H + blockIdx.x * UNITS + wu];
    }

    // --- one-time: rows [0,512) into registers (112 floats/thread) ---
    float4 wreg[NG * KREG];
#pragma unroll
    for (int g = 0; g < NG; ++g) {
#pragma unroll
        for (int k = 0; k < KREG; ++k) {
            const int i0 = 4 * (lane + 32 * k);
            const float* base = w_r + (size_t)(H + i0) * GW + g * H + n;
            wreg[g * KREG + k] = make_float4(base[0], base[GW],
                                             base[2 * (size_t)GW], base[3 * (size_t)GW]);
        }
    }
    __syncthreads();

    const float4* Wv = (const float4*)Ws + (w * NG) * (HSM / 4);

    float c_st = 0.0f, cb_st = 0.0f;  // per-unit recurrent state (valid in all lanes)

    for (int t = 0; t < T_STEPS; ++t) {
        // ---- input-only prefetch (in flight during the barrier wait) ----
        const int   e = __ldg(&event[t]);
        const float d = __ldg(&duration[t]);
        const float* prow = g_pre + (size_t)e * GW + n;
        float pregate[NG];
#pragma unroll
        for (int g = 0; g < NG; ++g)
            pregate[g] = __ldg(&prow[g * H]);

        // ---- wait for release of step t (read-only poll on g_step) ----
        if (t > 0) {
            if (tid == 0) {
                while (ld_acquire_u32(&g_step) < (unsigned)t) { }
            }
            __syncthreads();
        }

        // ---- broadcast h_d from L2 (written by other SMs) ----
        const float4* hp = (const float4*)(g_h + (t & 1) * H);
        float4 hx[8];
#pragma unroll
        for (int k = 0; k < 8; ++k) hx[k] = __ldcg(&hp[lane + 32 * k]);

        float acc[NG];
#pragma unroll
        for (int g = 0; g < NG; ++g) acc[g] = 0.0f;

        // rows [0,512): register-resident weights
#pragma unroll
        for (int k = 0; k < KREG; ++k) {
            const float4 h4 = hx[k];
#pragma unroll
            for (int g = 0; g < NG; ++g) {
                const float4 w4 = wreg[g * KREG + k];
                acc[g] = fmaf(w4.x, h4.x,
                         fmaf(w4.y, h4.y,
                         fmaf(w4.z, h4.z,
                         fmaf(w4.w, h4.w, acc[g]))));
            }
        }
        // rows [512,1024): SMEM-resident weights
#pragma unroll
        for (int k = 0; k < KSM; ++k) {
            const float4 h4 = hx[KREG + k];
#pragma unroll
            for (int g = 0; g < NG; ++g) {
                const float4 w4 = Wv[g * (HSM / 4) + lane + 32 * k];
                acc[g] = fmaf(w4.x, h4.x,
                         fmaf(w4.y, h4.y,
                         fmaf(w4.z, h4.z,
                         fmaf(w4.w, h4.w, acc[g]))));
            }
        }

        // warp reduction (all lanes end with full sums)
#pragma unroll
        for (int g = 0; g < NG; ++g) {
#pragma unroll
            for (int o = 16; o > 0; o >>= 1)
                acc[g] += __shfl_xor_sync(0xffffffffu, acc[g], o);
        }

        float gate[NG];
#pragma unroll
        for (int g = 0; g < NG; ++g)
            gate[g] = acc[g] + pregate[g];

        const float gi  = sigmoidf_(gate[0]);
        const float gf  = sigmoidf_(gate[1]);
        const float gz  = tanhf_(gate[2]);
        const float go  = sigmoidf_(gate[3]);
        const float gib = sigmoidf_(gate[4]);
        const float gfb = sigmoidf_(gate[5]);
        const float gdl = softplusf_(gate[6]);

        c_st  = gf  * c_st  + gi  * gz;
        cb_st = gfb * cb_st + gib * gz;
        const float h_t = go * tanhf_(c_st);
        const float cd  = cb_st + (c_st - cb_st) * __expf(-gdl * d);
        const float h_d = go * tanhf_(cd);

        if (lane == 0) {
            // critical value first
            g_h[((t + 1) & 1) * H + n] = h_d;
            const int TH = T_STEPS * H;
            float* o0 = out + t * H + n;
            o0[0 * TH] = h_t;
            o0[1 * TH] = c_st;
            o0[2 * TH] = cb_st;
            o0[3 * TH] = go;
            o0[4 * TH] = gdl;
        }

        __syncthreads();                 // all warps published their h_d
        if (tid == 0) {
            __threadfence();             // release h_d stores device-wide
            // arrive on the atomics-only line; last arriver opens the gate
            const unsigned old = atom_acqrel_add(&g_count, 1u);
            if (old == (unsigned)NB * (unsigned)(t + 1) - 1u)
                st_release_u32(&g_step, (unsigned)(t + 1));
        }
    }
}

// -------- launch --------
extern "C" void kernel_launch(void* const* d_in, const int* in_sizes, int n_in,
                              void* d_out, int out_size) {
    const int*   event    = (const int*)  d_in[0];
    const float* duration = (const float*)d_in[1];
    const float* w_r      = (const float*)d_in[2];
    const float* b_r      = (const float*)d_in[3];
    const float* emb      = (const float*)d_in[4];
    float*       out      = (float*)d_out;

    (void)in_sizes; (void)n_in; (void)out_size;

    const size_t smem = (size_t)WS_FLOATS * sizeof(float);  // 114688 B
    cudaFuncSetAttribute(ctlstm_kernel,
                         cudaFuncAttributeMaxDynamicSharedMemorySize,
                         (int)smem);

    pre_kernel<<<dim3(GW / NT, KROWS / KSUB), NT>>>(w_r, b_r, emb);
    ctlstm_kernel<<<NB, NT, smem>>>(event, duration, w_r, out);
}

// round 9
// speedup vs baseline: 1.9297x; 1.5573x over previous
#include <cuda_runtime.h>

#define T_STEPS 4096
#define H       1024
#define NG      7
#define GW      (NG * H)      // 7168 gate columns
#define KROWS   33
#define NB      128           // persistent blocks (1 per SM)
#define NT      256           // threads per block (8 warps)
#define UNITS   8             // hidden units per block
#define COLS    (UNITS * NG)  // 56 gate columns per block
#define KSUB    11            // emb rows per precompute block (3*11 = 33)

#define HREG    512                       // rows [0,512) live in registers
#define HSM     (H - HREG)                // 512 rows in SMEM
#define KREG    (HREG / 128)              // 4 float4 per lane per gate
#define KSM     (HSM / 128)               // 4 float4 per lane per gate
#define WS_FLOATS (COLS * HSM)            // 28672 floats = 112 KB
#define HS_OFF  WS_FLOATS                 // h staging area (1024 floats)
#define SMEM_FLOATS (WS_FLOATS + H)

// -------- device scratch (no allocations allowed) --------
__device__ float    g_pre[KROWS * GW];   // precomputed input contribution + bias
__device__ float    g_h[2 * H];          // double-buffered h_d
__device__ unsigned g_bar;               // global step counter (R6 proven design)

// -------- helpers --------
__device__ __forceinline__ unsigned ld_acquire_u32(const unsigned* p) {
    unsigned v;
    asm volatile("ld.acquire.gpu.u32 %0, [%1];" : "=r"(v) : "l"(p));
    return v;
}
__device__ __forceinline__ float sigmoidf_(float x) {
    return __fdividef(1.0f, 1.0f + __expf(-x));
}
__device__ __forceinline__ float tanhf_(float x) {
    return 1.0f - __fdividef(2.0f, __expf(2.0f * x) + 1.0f);
}
__device__ __forceinline__ float softplusf_(float x) {
    return fmaxf(x, 0.0f) + __logf(1.0f + __expf(-fabsf(x)));
}

// -------- kernel 1: pre[k][j] = emb[k] @ W_top[:,j] + b_r[j]  (+ state reset) --------
__global__ void pre_kernel(const float* __restrict__ w_r,
                           const float* __restrict__ b_r,
                           const float* __restrict__ emb) {
    // graph-replay determinism: block (0,0) resets persistent state
    if (blockIdx.x == 0 && blockIdx.y == 0) {
        if (threadIdx.x == 0) g_bar = 0u;
        for (int i = threadIdx.x; i < 2 * H; i += NT) g_h[i] = 0.0f;
    }

    __shared__ float es[KSUB * H];
    const int j  = blockIdx.x * NT + threadIdx.x;   // gate column
    const int k0 = blockIdx.y * KSUB;               // emb row base

    for (int idx = threadIdx.x; idx < KSUB * H; idx += NT)
        es[idx] = emb[k0 * H + idx];
    __syncthreads();

    float acc[KSUB];
#pragma unroll
    for (int k = 0; k < KSUB; ++k) acc[k] = 0.0f;

    const float4* es4 = (const float4*)es;
    for (int i4 = 0; i4 < H / 4; ++i4) {
        const int i = i4 * 4;
        const float w0 = w_r[(i + 0) * GW + j];
        const float w1 = w_r[(i + 1) * GW + j];
        const float w2 = w_r[(i + 2) * GW + j];
        const float w3 = w_r[(i + 3) * GW + j];
#pragma unroll
        for (int k = 0; k < KSUB; ++k) {
            float4 e = es4[k * (H / 4) + i4];
            acc[k] = fmaf(w0, e.x, fmaf(w1, e.y, fmaf(w2, e.z, fmaf(w3, e.w, acc[k]))));
        }
    }
    const float b = b_r[j];
#pragma unroll
    for (int k = 0; k < KSUB; ++k)
        g_pre[(k0 + k) * GW + j] = acc[k] + b;
}

// -------- kernel 2: persistent sequential CTLSTM --------
__global__ void __launch_bounds__(NT, 1)
ctlstm_kernel(const int*   __restrict__ event,
              const float* __restrict__ duration,
              const float* __restrict__ w_r,
              float*       __restrict__ out) {
    extern __shared__ float Ws[];   // [COLS][HSM] weights + h staging

    const int tid  = threadIdx.x;
    const int lane = tid & 31;
    const int w    = tid >> 5;                  // warp id 0..7 -> local unit
    const int n    = blockIdx.x * UNITS + w;    // global hidden unit

    // --- one-time: rows [512,1024) into SMEM ---
    for (int idx = tid; idx < WS_FLOATS; idx += NT) {
        const int c  = idx / HSM;
        const int ii = idx - c * HSM;
        const int wu = c / NG;
        const int g  = c - wu * NG;
        Ws[idx] = w_r[(size_t)(H + HREG + ii) * GW + g * H + blockIdx.x * UNITS + wu];
    }

    // --- one-time: rows [0,512) into registers (112 floats/thread) ---
    float4 wreg[NG * KREG];
#pragma unroll
    for (int g = 0; g < NG; ++g) {
#pragma unroll
        for (int k = 0; k < KREG; ++k) {
            const int i0 = 4 * (lane + 32 * k);
            const float* base = w_r + (size_t)(H + i0) * GW + g * H + n;
            wreg[g * KREG + k] = make_float4(base[0], base[GW],
                                             base[2 * (size_t)GW], base[3 * (size_t)GW]);
        }
    }
    __syncthreads();

    const float4* Wv = (const float4*)Ws + (w * NG) * (HSM / 4);
    float4* hs4      = (float4*)(Ws + HS_OFF);

    float c_st = 0.0f, cb_st = 0.0f;  // per-unit recurrent state (valid in all lanes)

    for (int t = 0; t < T_STEPS; ++t) {
        // ---- input-only prefetch (in flight during the barrier wait) ----
        const int   e = __ldg(&event[t]);
        const float d = __ldg(&duration[t]);
        const float* prow = g_pre + (size_t)e * GW + n;
        float pregate[NG];
#pragma unroll
        for (int g = 0; g < NG; ++g)
            pregate[g] = __ldg(&prow[g * H]);

        // ---- wait for all blocks to finish step t-1 (single poller, proven) ----
        if (t > 0) {
            if (tid == 0) {
                const unsigned tgt = (unsigned)NB * (unsigned)t;
                while (ld_acquire_u32(&g_bar) < tgt) { }
            }
            __syncthreads();
        }

        // ---- stage h once per block: 4KB from L2 instead of 32KB ----
        {
            const float4* hp4 = (const float4*)(g_h + (t & 1) * H);
            hs4[tid] = __ldcg(&hp4[tid]);
        }
        __syncthreads();

        // h values this thread consumes (shared across the 7 gates)
        float4 hx[8];
#pragma unroll
        for (int k = 0; k < 8; ++k) hx[k] = hs4[lane + 32 * k];

        float acc[NG];
#pragma unroll
        for (int g = 0; g < NG; ++g) acc[g] = 0.0f;

        // rows [0,512): register-resident weights
#pragma unroll
        for (int k = 0; k < KREG; ++k) {
            const float4 h4 = hx[k];
#pragma unroll
            for (int g = 0; g < NG; ++g) {
                const float4 w4 = wreg[g * KREG + k];
                acc[g] = fmaf(w4.x, h4.x,
                         fmaf(w4.y, h4.y,
                         fmaf(w4.z, h4.z,
                         fmaf(w4.w, h4.w, acc[g]))));
            }
        }
        // rows [512,1024): SMEM-resident weights
#pragma unroll
        for (int k = 0; k < KSM; ++k) {
            const float4 h4 = hx[KREG + k];
#pragma unroll
            for (int g = 0; g < NG; ++g) {
                const float4 w4 = Wv[g * (HSM / 4) + lane + 32 * k];
                acc[g] = fmaf(w4.x, h4.x,
                         fmaf(w4.y, h4.y,
                         fmaf(w4.z, h4.z,
                         fmaf(w4.w, h4.w, acc[g]))));
            }
        }

        // warp reduction (all lanes end with full sums)
#pragma unroll
        for (int g = 0; g < NG; ++g) {
#pragma unroll
            for (int o = 16; o > 0; o >>= 1)
                acc[g] += __shfl_xor_sync(0xffffffffu, acc[g], o);
        }

        float gate[NG];
#pragma unroll
        for (int g = 0; g < NG; ++g)
            gate[g] = acc[g] + pregate[g];

        const float gi  = sigmoidf_(gate[0]);
        const float gf  = sigmoidf_(gate[1]);
        const float gz  = tanhf_(gate[2]);
        const float go  = sigmoidf_(gate[3]);
        const float gib = sigmoidf_(gate[4]);
        const float gfb = sigmoidf_(gate[5]);
        const float gdl = softplusf_(gate[6]);

        c_st  = gf  * c_st  + gi  * gz;
        cb_st = gfb * cb_st + gib * gz;
        const float h_t = go * tanhf_(c_st);
        const float cd  = cb_st + (c_st - cb_st) * __expf(-gdl * d);
        const float h_d = go * tanhf_(cd);

        if (lane == 0) {
            // critical value first
            g_h[((t + 1) & 1) * H + n] = h_d;
            const int TH = T_STEPS * H;
            float* o0 = out + t * H + n;
            o0[0 * TH] = h_t;
            o0[1 * TH] = c_st;
            o0[2 * TH] = cb_st;
            o0[3 * TH] = go;
            o0[4 * TH] = gdl;
        }

        __syncthreads();                 // all warps published their h_d
        if (tid == 0) {
            __threadfence();             // release h_d stores device-wide
            atomicAdd(&g_bar, 1u);       // arrive (R6 proven barrier)
        }
    }
}

// -------- launch --------
extern "C" void kernel_launch(void* const* d_in, const int* in_sizes, int n_in,
                              void* d_out, int out_size) {
    const int*   event    = (const int*)  d_in[0];
    const float* duration = (const float*)d_in[1];
    const float* w_r      = (const float*)d_in[2];
    const float* b_r      = (const float*)d_in[3];
    const float* emb      = (const float*)d_in[4];
    float*       out      = (float*)d_out;

    (void)in_sizes; (void)n_in; (void)out_size;

    const size_t smem = (size_t)SMEM_FLOATS * sizeof(float);  // 118784 B
    cudaFuncSetAttribute(ctlstm_kernel,
                         cudaFuncAttributeMaxDynamicSharedMemorySize,
                         (int)smem);

    pre_kernel<<<dim3(GW / NT, KROWS / KSUB), NT>>>(w_r, b_r, emb);
    ctlstm_kernel<<<NB, NT, smem>>>(event, duration, w_r, out);
}

// round 10
// speedup vs baseline: 1.9382x; 1.0044x over previous
#include <cuda_runtime.h>

#define T_STEPS 4096
#define H       1024
#define NG      7
#define GW      (NG * H)      // 7168 gate columns
#define KROWS   33
#define NB      128           // persistent blocks (1 per SM)
#define NT      256           // threads per block (8 warps)
#define UNITS   8             // hidden units per block
#define COLS    (UNITS * NG)  // 56 gate columns per block
#define KSUB    11            // emb rows per precompute block (3*11 = 33)

#define HREG    512                       // rows [0,512) live in registers
#define HSM     (H - HREG)                // 512 rows in SMEM
#define KREG    (HREG / 128)              // 4 float4 per lane per gate
#define KSM     (HSM / 128)               // 4 float4 per lane per gate
#define WS_FLOATS (COLS * HSM)            // 28672 floats = 112 KB
#define HS_OFF  WS_FLOATS                 // h staging area (1024 floats)
#define SMEM_FLOATS (WS_FLOATS + H)

typedef unsigned long long u64;

// -------- device scratch (no allocations allowed) --------
__device__ float    g_pre[KROWS * GW];   // precomputed input contribution + bias
__device__ float    g_h[2 * H];          // double-buffered h_d
__device__ unsigned g_bar;               // global step counter (proven design)

// -------- helpers --------
__device__ __forceinline__ unsigned ld_acquire_u32(const unsigned* p) {
    unsigned v;
    asm volatile("ld.acquire.gpu.u32 %0, [%1];" : "=r"(v) : "l"(p));
    return v;
}
__device__ __forceinline__ u64 pack_f32x2(float lo, float hi) {
    u64 r;
    asm("mov.b64 %0, {%1, %2};" : "=l"(r) : "f"(lo), "f"(hi));
    return r;
}
__device__ __forceinline__ void fma2(u64& d, u64 a, u64 b) {
    asm("fma.rn.f32x2 %0, %1, %2, %3;" : "=l"(d) : "l"(a), "l"(b), "l"(d));
}
__device__ __forceinline__ float2 unpack_f32x2(u64 v) {
    float lo, hi;
    asm("mov.b64 {%0, %1}, %2;" : "=f"(lo), "=f"(hi) : "l"(v));
    return make_float2(lo, hi);
}
__device__ __forceinline__ float sigmoidf_(float x) {
    return __fdividef(1.0f, 1.0f + __expf(-x));
}
__device__ __forceinline__ float tanhf_(float x) {
    return 1.0f - __fdividef(2.0f, __expf(2.0f * x) + 1.0f);
}
__device__ __forceinline__ float softplusf_(float x) {
    return fmaxf(x, 0.0f) + __logf(1.0f + __expf(-fabsf(x)));
}

// -------- kernel 1: pre[k][j] = emb[k] @ W_top[:,j] + b_r[j]  (+ state reset) --------
__global__ void pre_kernel(const float* __restrict__ w_r,
                           const float* __restrict__ b_r,
                           const float* __restrict__ emb) {
    // graph-replay determinism: block (0,0) resets persistent state
    if (blockIdx.x == 0 && blockIdx.y == 0) {
        if (threadIdx.x == 0) g_bar = 0u;
        for (int i = threadIdx.x; i < 2 * H; i += NT) g_h[i] = 0.0f;
    }

    __shared__ float es[KSUB * H];
    const int j  = blockIdx.x * NT + threadIdx.x;   // gate column
    const int k0 = blockIdx.y * KSUB;               // emb row base

    for (int idx = threadIdx.x; idx < KSUB * H; idx += NT)
        es[idx] = emb[k0 * H + idx];
    __syncthreads();

    float acc[KSUB];
#pragma unroll
    for (int k = 0; k < KSUB; ++k) acc[k] = 0.0f;

    const float4* es4 = (const float4*)es;
    for (int i4 = 0; i4 < H / 4; ++i4) {
        const int i = i4 * 4;
        const float w0 = w_r[(i + 0) * GW + j];
        const float w1 = w_r[(i + 1) * GW + j];
        const float w2 = w_r[(i + 2) * GW + j];
        const float w3 = w_r[(i + 3) * GW + j];
#pragma unroll
        for (int k = 0; k < KSUB; ++k) {
            float4 e = es4[k * (H / 4) + i4];
            acc[k] = fmaf(w0, e.x, fmaf(w1, e.y, fmaf(w2, e.z, fmaf(w3, e.w, acc[k]))));
        }
    }
    const float b = b_r[j];
#pragma unroll
    for (int k = 0; k < KSUB; ++k)
        g_pre[(k0 + k) * GW + j] = acc[k] + b;
}

// -------- kernel 2: persistent sequential CTLSTM --------
__global__ void __launch_bounds__(NT, 1)
ctlstm_kernel(const int*   __restrict__ event,
              const float* __restrict__ duration,
              const float* __restrict__ w_r,
              float*       __restrict__ out) {
    extern __shared__ float Ws[];   // [COLS][HSM] weights + h staging

    const int tid  = threadIdx.x;
    const int lane = tid & 31;
    const int w    = tid >> 5;                  // warp id 0..7 -> local unit
    const int n    = blockIdx.x * UNITS + w;    // global hidden unit

    // --- one-time: rows [512,1024) into SMEM ---
    for (int idx = tid; idx < WS_FLOATS; idx += NT) {
        const int c  = idx / HSM;
        const int ii = idx - c * HSM;
        const int wu = c / NG;
        const int g  = c - wu * NG;
        Ws[idx] = w_r[(size_t)(H + HREG + ii) * GW + g * H + blockIdx.x * UNITS + wu];
    }

    // --- one-time: rows [0,512) into registers, packed as f32x2 pairs ---
    u64 wreg[NG * KREG * 2];
#pragma unroll
    for (int g = 0; g < NG; ++g) {
#pragma unroll
        for (int k = 0; k < KREG; ++k) {
            const int i0 = 4 * (lane + 32 * k);
            const float* base = w_r + (size_t)(H + i0) * GW + g * H + n;
            wreg[(g * KREG + k) * 2 + 0] = pack_f32x2(base[0], base[GW]);
            wreg[(g * KREG + k) * 2 + 1] = pack_f32x2(base[2 * (size_t)GW], base[3 * (size_t)GW]);
        }
    }
    __syncthreads();

    const ulonglong2* Wv = (const ulonglong2*)Ws + (w * NG) * (HSM / 4);
    float4*           hs4 = (float4*)(Ws + HS_OFF);
    const ulonglong2* hsu = (const ulonglong2*)(Ws + HS_OFF);

    float c_st = 0.0f, cb_st = 0.0f;  // per-unit recurrent state (valid in all lanes)

    for (int t = 0; t < T_STEPS; ++t) {
        // ---- input-only prefetch (in flight during the barrier wait) ----
        const int   e = __ldg(&event[t]);
        const float d = __ldg(&duration[t]);
        const float* prow = g_pre + (size_t)e * GW + n;
        float pregate[NG];
#pragma unroll
        for (int g = 0; g < NG; ++g)
            pregate[g] = __ldg(&prow[g * H]);

        // ---- wait for all blocks to finish step t-1 (single poller, proven) ----
        if (t > 0) {
            if (tid == 0) {
                const unsigned tgt = (unsigned)NB * (unsigned)t;
                while (ld_acquire_u32(&g_bar) < tgt) { }
            }
            __syncthreads();
        }

        // ---- stage h once per block: 4KB from L2 instead of 32KB ----
        {
            const float4* hp4 = (const float4*)(g_h + (t & 1) * H);
            hs4[tid] = __ldcg(&hp4[tid]);
        }
        __syncthreads();

        // h values this thread consumes, as packed f32x2 pairs
        ulonglong2 hx[8];
#pragma unroll
        for (int k = 0; k < 8; ++k) hx[k] = hsu[lane + 32 * k];

        u64 acc2[NG];
#pragma unroll
        for (int g = 0; g < NG; ++g) acc2[g] = 0ull;   // (0.0f, 0.0f)

        // rows [0,512): register-resident packed weights
#pragma unroll
        for (int k = 0; k < KREG; ++k) {
            const ulonglong2 h2 = hx[k];
#pragma unroll
            for (int g = 0; g < NG; ++g) {
                fma2(acc2[g], wreg[(g * KREG + k) * 2 + 0], h2.x);
                fma2(acc2[g], wreg[(g * KREG + k) * 2 + 1], h2.y);
            }
        }
        // rows [512,1024): SMEM-resident packed weights
#pragma unroll
        for (int k = 0; k < KSM; ++k) {
            const ulonglong2 h2 = hx[KREG + k];
#pragma unroll
            for (int g = 0; g < NG; ++g) {
                const ulonglong2 w2 = Wv[g * (HSM / 4) + lane + 32 * k];
                fma2(acc2[g], w2.x, h2.x);
                fma2(acc2[g], w2.y, h2.y);
            }
        }

        // collapse packed pairs, then warp reduction
        float acc[NG];
#pragma unroll
        for (int g = 0; g < NG; ++g) {
            const float2 p = unpack_f32x2(acc2[g]);
            acc[g] = p.x + p.y;
        }
#pragma unroll
        for (int g = 0; g < NG; ++g) {
#pragma unroll
            for (int o = 16; o > 0; o >>= 1)
                acc[g] += __shfl_xor_sync(0xffffffffu, acc[g], o);
        }

        float gate[NG];
#pragma unroll
        for (int g = 0; g < NG; ++g)
            gate[g] = acc[g] + pregate[g];

        const float gi  = sigmoidf_(gate[0]);
        const float gf  = sigmoidf_(gate[1]);
        const float gz  = tanhf_(gate[2]);
        const float go  = sigmoidf_(gate[3]);
        const float gib = sigmoidf_(gate[4]);
        const float gfb = sigmoidf_(gate[5]);
        const float gdl = softplusf_(gate[6]);

        c_st  = gf  * c_st  + gi  * gz;
        cb_st = gfb * cb_st + gib * gz;
        const float h_t = go * tanhf_(c_st);
        const float cd  = cb_st + (c_st - cb_st) * __expf(-gdl * d);
        const float h_d = go * tanhf_(cd);

        if (lane == 0) {
            // critical value first
            g_h[((t + 1) & 1) * H + n] = h_d;
            const int TH = T_STEPS * H;
            float* o0 = out + t * H + n;
            o0[0 * TH] = h_t;
            o0[1 * TH] = c_st;
            o0[2 * TH] = cb_st;
            o0[3 * TH] = go;
            o0[4 * TH] = gdl;
        }

        __syncthreads();                 // all warps published their h_d
        if (tid == 0) {
            __threadfence();             // release h_d stores device-wide
            atomicAdd(&g_bar, 1u);       // arrive (proven barrier)
        }
    }
}

// -------- launch --------
extern "C" void kernel_launch(void* const* d_in, const int* in_sizes, int n_in,
                              void* d_out, int out_size) {
    const int*   event    = (const int*)  d_in[0];
    const float* duration = (const float*)d_in[1];
    const float* w_r      = (const float*)d_in[2];
    const float* b_r      = (const float*)d_in[3];
    const float* emb      = (const float*)d_in[4];
    float*       out      = (float*)d_out;

    (void)in_sizes; (void)n_in; (void)out_size;

    const size_t smem = (size_t)SMEM_FLOATS * sizeof(float);  // 118784 B
    cudaFuncSetAttribute(ctlstm_kernel,
                         cudaFuncAttributeMaxDynamicSharedMemorySize,
                         (int)smem);

    pre_kernel<<<dim3(GW / NT, KROWS / KSUB), NT>>>(w_r, b_r, emb);
    ctlstm_kernel<<<NB, NT, smem>>>(event, duration, w_r, out);
}

// round 11
// speedup vs baseline: 2.1189x; 1.0932x over previous
#include <cuda_runtime.h>

#define T_STEPS 4096
#define H       1024
#define NG      7
#define GW      (NG * H)      // 7168 gate columns
#define KROWS   33
#define NB      128           // persistent blocks (1 per SM)
#define NT      256           // threads per block (8 warps)
#define UNITS   8             // hidden units per block
#define COLS    (UNITS * NG)  // 56 gate columns per block
#define KSUB    11            // emb rows per precompute block (3*11 = 33)

#define HREG    512                       // rows [0,512) live in registers
#define HSM     (H - HREG)                // 512 rows in SMEM
#define KREG    (HREG / 128)              // 4 float4 per lane per gate
#define KSM     (HSM / 128)               // 4 float4 per lane per gate
#define WS_FLOATS (COLS * HSM)            // 28672 floats = 112 KB
#define HS_OFF  WS_FLOATS                 // h staging area (1024 floats)
#define SMEM_FLOATS (WS_FLOATS + H)

typedef unsigned long long u64;

// -------- device scratch (no allocations allowed) --------
__device__ float    g_pre[KROWS * GW];   // precomputed input contribution + bias
__device__ float    g_h[2 * H];          // double-buffered h_d
__device__ unsigned g_bar;               // global step counter (proven design)

// -------- helpers --------
__device__ __forceinline__ unsigned ld_acquire_u32(const unsigned* p) {
    unsigned v;
    asm volatile("ld.acquire.gpu.u32 %0, [%1];" : "=r"(v) : "l"(p));
    return v;
}
__device__ __forceinline__ void red_release_add(unsigned* p, unsigned v) {
    asm volatile("red.release.gpu.global.add.u32 [%0], %1;" :: "l"(p), "r"(v) : "memory");
}
__device__ __forceinline__ u64 pack_f32x2(float lo, float hi) {
    u64 r;
    asm("mov.b64 %0, {%1, %2};" : "=l"(r) : "f"(lo), "f"(hi));
    return r;
}
__device__ __forceinline__ void fma2(u64& d, u64 a, u64 b) {
    asm("fma.rn.f32x2 %0, %1, %2, %3;" : "=l"(d) : "l"(a), "l"(b), "l"(d));
}
__device__ __forceinline__ float2 unpack_f32x2(u64 v) {
    float lo, hi;
    asm("mov.b64 {%0, %1}, %2;" : "=f"(lo), "=f"(hi) : "l"(v));
    return make_float2(lo, hi);
}
__device__ __forceinline__ float sigmoidf_(float x) {
    return __fdividef(1.0f, 1.0f + __expf(-x));
}
__device__ __forceinline__ float tanhf_(float x) {
    return 1.0f - __fdividef(2.0f, __expf(2.0f * x) + 1.0f);
}
__device__ __forceinline__ float softplusf_(float x) {
    return fmaxf(x, 0.0f) + __logf(1.0f + __expf(-fabsf(x)));
}

// -------- kernel 1: pre[k][j] = emb[k] @ W_top[:,j] + b_r[j]  (+ state reset) --------
__global__ void pre_kernel(const float* __restrict__ w_r,
                           const float* __restrict__ b_r,
                           const float* __restrict__ emb) {
    // graph-replay determinism: block (0,0) resets persistent state
    if (blockIdx.x == 0 && blockIdx.y == 0) {
        if (threadIdx.x == 0) g_bar = 0u;
        for (int i = threadIdx.x; i < 2 * H; i += NT) g_h[i] = 0.0f;
    }

    __shared__ float es[KSUB * H];
    const int j  = blockIdx.x * NT + threadIdx.x;   // gate column
    const int k0 = blockIdx.y * KSUB;               // emb row base

    for (int idx = threadIdx.x; idx < KSUB * H; idx += NT)
        es[idx] = emb[k0 * H + idx];
    __syncthreads();

    float acc[KSUB];
#pragma unroll
    for (int k = 0; k < KSUB; ++k) acc[k] = 0.0f;

    const float4* es4 = (const float4*)es;
    for (int i4 = 0; i4 < H / 4; ++i4) {
        const int i = i4 * 4;
        const float w0 = w_r[(i + 0) * GW + j];
        const float w1 = w_r[(i + 1) * GW + j];
        const float w2 = w_r[(i + 2) * GW + j];
        const float w3 = w_r[(i + 3) * GW + j];
#pragma unroll
        for (int k = 0; k < KSUB; ++k) {
            float4 e = es4[k * (H / 4) + i4];
            acc[k] = fmaf(w0, e.x, fmaf(w1, e.y, fmaf(w2, e.z, fmaf(w3, e.w, acc[k]))));
        }
    }
    const float b = b_r[j];
#pragma unroll
    for (int k = 0; k < KSUB; ++k)
        g_pre[(k0 + k) * GW + j] = acc[k] + b;
}

// -------- kernel 2: persistent sequential CTLSTM --------
__global__ void __launch_bounds__(NT, 1)
ctlstm_kernel(const int*   __restrict__ event,
              const float* __restrict__ duration,
              const float* __restrict__ w_r,
              float*       __restrict__ out) {
    extern __shared__ float Ws[];   // [COLS][HSM] weights + h staging

    const int tid  = threadIdx.x;
    const int lane = tid & 31;
    const int w    = tid >> 5;                  // warp id 0..7 -> local unit
    const int n    = blockIdx.x * UNITS + w;    // global hidden unit

    // --- one-time: rows [512,1024) into SMEM ---
    for (int idx = tid; idx < WS_FLOATS; idx += NT) {
        const int c  = idx / HSM;
        const int ii = idx - c * HSM;
        const int wu = c / NG;
        const int g  = c - wu * NG;
        Ws[idx] = w_r[(size_t)(H + HREG + ii) * GW + g * H + blockIdx.x * UNITS + wu];
    }

    // --- one-time: rows [0,512) into registers, packed as f32x2 pairs ---
    u64 wreg[NG * KREG * 2];
#pragma unroll
    for (int g = 0; g < NG; ++g) {
#pragma unroll
        for (int k = 0; k < KREG; ++k) {
            const int i0 = 4 * (lane + 32 * k);
            const float* base = w_r + (size_t)(H + i0) * GW + g * H + n;
            wreg[(g * KREG + k) * 2 + 0] = pack_f32x2(base[0], base[GW]);
            wreg[(g * KREG + k) * 2 + 1] = pack_f32x2(base[2 * (size_t)GW], base[3 * (size_t)GW]);
        }
    }
    __syncthreads();

    const ulonglong2* Wv = (const ulonglong2*)Ws + (w * NG) * (HSM / 4);
    float4*           hs4 = (float4*)(Ws + HS_OFF);
    const ulonglong2* hsu = (const ulonglong2*)(Ws + HS_OFF);

    float c_st = 0.0f, cb_st = 0.0f;  // per-unit recurrent state (valid in all lanes)

    for (int t = 0; t < T_STEPS; ++t) {
        // ---- input-only prefetch (in flight during the barrier wait) ----
        const int   e = __ldg(&event[t]);
        const float d = __ldg(&duration[t]);
        const float* prow = g_pre + (size_t)e * GW + n;
        float pregate[NG];
#pragma unroll
        for (int g = 0; g < NG; ++g)
            pregate[g] = __ldg(&prow[g * H]);

        // ---- wait for all blocks to finish step t-1 (single poller, proven) ----
        if (t > 0) {
            if (tid == 0) {
                const unsigned tgt = (unsigned)NB * (unsigned)t;
                while (ld_acquire_u32(&g_bar) < tgt) { }
            }
            __syncthreads();
        }

        // ---- stage h once per block: 4KB from L2 instead of 32KB ----
        {
            const float4* hp4 = (const float4*)(g_h + (t & 1) * H);
            hs4[tid] = __ldcg(&hp4[tid]);
        }
        __syncthreads();

        // h values this thread consumes, as packed f32x2 pairs
        ulonglong2 hx[8];
#pragma unroll
        for (int k = 0; k < 8; ++k) hx[k] = hsu[lane + 32 * k];

        u64 acc2[NG];
#pragma unroll
        for (int g = 0; g < NG; ++g) acc2[g] = 0ull;   // (0.0f, 0.0f)

        // rows [0,512): register-resident packed weights
#pragma unroll
        for (int k = 0; k < KREG; ++k) {
            const ulonglong2 h2 = hx[k];
#pragma unroll
            for (int g = 0; g < NG; ++g) {
                fma2(acc2[g], wreg[(g * KREG + k) * 2 + 0], h2.x);
                fma2(acc2[g], wreg[(g * KREG + k) * 2 + 1], h2.y);
            }
        }
        // rows [512,1024): SMEM-resident packed weights
#pragma unroll
        for (int k = 0; k < KSM; ++k) {
            const ulonglong2 h2 = hx[KREG + k];
#pragma unroll
            for (int g = 0; g < NG; ++g) {
                const ulonglong2 w2 = Wv[g * (HSM / 4) + lane + 32 * k];
                fma2(acc2[g], w2.x, h2.x);
                fma2(acc2[g], w2.y, h2.y);
            }
        }

        // collapse packed pairs, then warp reduction
        float acc[NG];
#pragma unroll
        for (int g = 0; g < NG; ++g) {
            const float2 p = unpack_f32x2(acc2[g]);
            acc[g] = p.x + p.y;
        }
#pragma unroll
        for (int g = 0; g < NG; ++g) {
#pragma unroll
            for (int o = 16; o > 0; o >>= 1)
                acc[g] += __shfl_xor_sync(0xffffffffu, acc[g], o);
        }

        float gate[NG];
#pragma unroll
        for (int g = 0; g < NG; ++g)
            gate[g] = acc[g] + pregate[g];

        // ---- epilogue, h_d-first ordering (shortest release chain) ----
        const float gdl = softplusf_(gate[6]);
        const float go  = sigmoidf_(gate[3]);
        const float gi  = sigmoidf_(gate[0]);
        const float gf  = sigmoidf_(gate[1]);
        const float gz  = tanhf_(gate[2]);
        const float gib = sigmoidf_(gate[4]);
        const float gfb = sigmoidf_(gate[5]);

        const float edl = __expf(-gdl * d);          // starts as soon as gdl ready
        c_st  = gf  * c_st  + gi  * gz;
        cb_st = gfb * cb_st + gib * gz;
        const float cd  = cb_st + (c_st - cb_st) * edl;
        const float h_d = go * tanhf_(cd);

        if (lane == 0)
            g_h[((t + 1) & 1) * H + n] = h_d;        // the ONLY store gating release

        const float h_t = go * tanhf_(c_st);         // off the release chain

        __syncthreads();                 // all warps published their h_d
        if (tid == 0)
            red_release_add(&g_bar, 1u); // release-arrive (no full membar)

        // ---- post-release shadow: out stores drain during others' poll window ----
        if (lane == 0) {
            const int TH = T_STEPS * H;
            float* o0 = out + t * H + n;
            o0[0 * TH] = h_t;
            o0[1 * TH] = c_st;
            o0[2 * TH] = cb_st;
            o0[3 * TH] = go;
            o0[4 * TH] = gdl;
        }
    }
}

// -------- launch --------
extern "C" void kernel_launch(void* const* d_in, const int* in_sizes, int n_in,
                              void* d_out, int out_size) {
    const int*   event    = (const int*)  d_in[0];
    const float* duration = (const float*)d_in[1];
    const float* w_r      = (const float*)d_in[2];
    const float* b_r      = (const float*)d_in[3];
    const float* emb      = (const float*)d_in[4];
    float*       out      = (float*)d_out;

    (void)in_sizes; (void)n_in; (void)out_size;

    const size_t smem = (size_t)SMEM_FLOATS * sizeof(float);  // 118784 B
    cudaFuncSetAttribute(ctlstm_kernel,
                         cudaFuncAttributeMaxDynamicSharedMemorySize,
                         (int)smem);

    pre_kernel<<<dim3(GW / NT, KROWS / KSUB), NT>>>(w_r, b_r, emb);
    ctlstm_kernel<<<NB, NT, smem>>>(event, duration, w_r, out);
}